// round 14
// baseline (speedup 1.0000x reference)
#include <cuda_runtime.h>
#include <stdint.h>
#include <math.h>

#define TT 256
#define BB 16
#define DD 512
#define NN 4096
#define HRR 256
#define BN_EPS 1e-5f

// ---------------- device scratch ----------------
__device__ float g_gi_r [NN * 768];
__device__ float g_gi_e1[NN * 384];
__device__ float g_gi_e2[NN * 768];
__device__ float g_gi_e3[NN * 1536];
__device__ float g_Hr[NN * HRR];
__device__ float g_H1[NN * 128];
__device__ float g_H2[NN * 256];
__device__ float g_H3[NN * 512];
__device__ float g_gates[NN * 4];
__device__ unsigned g_girdy[4 * 64];
__device__ float g_bnPS [8][896];
__device__ float g_bnPS2[8][896];
__device__ float g_bnA[3][512];
__device__ float g_bnB[3][512];
__device__ float g_tsum[4];
__device__ unsigned g_tcnt[4];

__device__ __forceinline__ float sigf(float x) { return 1.f / (1.f + __expf(-x)); }
__device__ __forceinline__ float tanhfast(float x) {
    float xc = fminf(fmaxf(x, -9.f), 9.f);
    float e = __expf(2.f * xc);
    return __fdividef(e - 1.f, e + 1.f);
}
__device__ __forceinline__ unsigned long long fma2(unsigned long long a, unsigned long long b,
                                                   unsigned long long c) {
    unsigned long long d;
    asm("fma.rn.f32x2 %0, %1, %2, %3;" : "=l"(d) : "l"(a), "l"(b), "l"(c));
    return d;
}

__device__ __forceinline__ void st_pair_cluster(uint32_t laddr, int rank, unsigned long long x) {
    uint32_t ra;
    asm volatile("mapa.shared::cluster.u32 %0, %1, %2;" : "=r"(ra) : "r"(laddr), "r"(rank));
    asm volatile("st.shared::cluster.b64 [%0], %1;" :: "r"(ra), "l"(x) : "memory");
}
__device__ __forceinline__ void ld_pair2_sh(uint32_t laddr, unsigned long long& a,
                                            unsigned long long& b) {
    asm volatile("ld.volatile.shared.v2.b64 {%0, %1}, [%2];" : "=l"(a), "=l"(b) : "r"(laddr));
}
__device__ __forceinline__ unsigned ld_acq(const unsigned* p) {
    unsigned v;
    asm volatile("ld.acquire.gpu.global.u32 %0, [%1];" : "=r"(v) : "l"(p) : "memory");
    return v;
}
__device__ __forceinline__ void red_rel(unsigned* p) {
    asm volatile("red.release.gpu.global.add.u32 [%0], 1;" :: "l"(p) : "memory");
}
#define CLUSTER_SYNC() do { \
    asm volatile("barrier.cluster.arrive.aligned;" ::: "memory"); \
    asm volatile("barrier.cluster.wait.aligned;" ::: "memory"); } while (0)

// ---------------- zero ----------------
__global__ void k_zero() {
    int i = threadIdx.x;
    if (i < 256) g_girdy[i] = 0u;
    if (i < 4) { g_tsum[i] = 0.f; g_tcnt[i] = 0u; }
}

// ---------------- expert recurrence: BARRIER-FREE dataflow exchange ----------------
// Ring pairs[2*H]: slot(par,k) = {h value, tag}. Step t consumes ring[pr=(t&1)^1]
// with tag t, publishes h(t) to ring[pw=t&1] with tag t+1. Lane owns interleaved
// pairs k=(2*linj + 2*LPJ*p); a 16B volatile v2.b64 load returns both {val,tag}
// words -> spin until both tags==t, pack values to f32x2, FMA2. No __syncthreads:
// 2-parity reuse is safe because each warp consumes the FULL ring every step.
template <int H, int NC, int JW>
__device__ void expert_recur(int cta, int base_rank,
                             const float* __restrict__ Whh, const float* __restrict__ bhh,
                             const float* gi, float* __restrict__ Hbuf,
                             const unsigned* rdy, int nbk, uint32_t pairs_addr)
{
    constexpr int JPC = H / NC;
    constexpr int LPJ = 32 / JW;
    constexpr int STR = 2 * LPJ;        // k stride between owned pairs
    constexpr int KP  = H / STR;        // pairs per lane
    const int tid = threadIdx.x, w = tid >> 5, lane = tid & 31;
    const int jj   = lane / LPJ;
    const int linj = lane % LPJ;
    const int j    = cta * JPC + w * JW + jj;
    const int kp0  = 2 * linj;

    unsigned long long wp[3][KP];
#pragma unroll
    for (int g = 0; g < 3; g++)
#pragma unroll
        for (int p = 0; p < KP; p++) {
            int k = kp0 + STR * p;
            unsigned lo = __float_as_uint(Whh[(size_t)(g * H + j) * H + k]);
            unsigned hi = __float_as_uint(Whh[(size_t)(g * H + j) * H + k + 1]);
            wp[g][p] = (unsigned long long)lo | ((unsigned long long)hi << 32);
        }
    const float bhn = bhh[2 * H + j];
    float hprev = 0.f;

    while (ld_acq(&rdy[0]) < (unsigned)nbk) {}
    int rdyw = 1;
    float gr0 = gi[j], gr1 = gi[H + j], gr2 = gi[2 * H + j];

    for (int t = 0; t < NN; t++) {
        const int pr = (t & 1) ^ 1;          // consume ring (h(t-1), tag t)
        const int pw = t & 1;                // publish ring (h(t), tag t+1)
        const unsigned tagc = (unsigned)t;
        unsigned long long acc[3] = {0ull, 0ull, 0ull};
        const uint32_t rb = pairs_addr + (uint32_t)(pr * H * 8);
#pragma unroll
        for (int p = 0; p < KP; p++) {
            uint32_t la = rb + (uint32_t)((kp0 + STR * p) * 8);
            unsigned long long w0, w1;
            do { ld_pair2_sh(la, w0, w1); }
            while ((unsigned)(w0 >> 32) != tagc || (unsigned)(w1 >> 32) != tagc);
            unsigned long long hp = (w0 & 0xffffffffull) | (w1 << 32);
#pragma unroll
            for (int g = 0; g < 3; g++) acc[g] = fma2(wp[g][p], hp, acc[g]);
        }
        float s[3];
#pragma unroll
        for (int g = 0; g < 3; g++)
            s[g] = __uint_as_float((unsigned)acc[g]) + __uint_as_float((unsigned)(acc[g] >> 32));
#pragma unroll
        for (int off = LPJ / 2; off > 0; off >>= 1)
#pragma unroll
            for (int g = 0; g < 3; g++) s[g] += __shfl_xor_sync(0xffffffffu, s[g], off);

        float r = sigf(gr0 + s[0]);
        float z = sigf(gr1 + s[1]);
        float n = tanhfast(gr2 + r * (s[2] + bhn));
        float hn = (1.f - z) * n + z * hprev;
        hprev = hn;

        if (linj < NC) {
            unsigned long long x =
                ((unsigned long long)(unsigned)(t + 1) << 32) |
                (unsigned long long)__float_as_uint(hn);
            uint32_t la = pairs_addr + (uint32_t)((pw * H + j) * 8);
            st_pair_cluster(la, base_rank + linj, x);
        }
        if (linj == 0) Hbuf[(size_t)t * H + j] = hn;

        // gated gi prefetch for t+1
        {
            int tn = (t + 1 < NN) ? t + 1 : t;
            int blk = tn >> 6;
            if (blk >= rdyw) {
                while (ld_acq(&rdy[blk]) < (unsigned)nbk) {}
                rdyw = blk + 1;
            }
            const float* gin = gi + (size_t)tn * 3 * H;
            gr0 = gin[j]; gr1 = gin[H + j]; gr2 = gin[2 * H + j];
        }
    }
}

// ---------------- router recurrence (+ readiness gating) ----------------
__device__ void router_recur(int b, const float* __restrict__ Whh, const float* __restrict__ bhh,
                             const unsigned* rdy, int nbk, float* cur, float* nxt)
{
    const int tid = threadIdx.x, w = tid >> 5, lane = tid & 31;
    const int j0 = w * 16;
    __syncthreads();
    int rdyw = 0;

    for (int t = 0; t < TT; t++) {
        const int n = t * BB + b;
        int blk = n >> 6;
        if (blk >= rdyw) {
            while (ld_acq(&rdy[blk]) < (unsigned)nbk) {}
            rdyw = blk + 1;
        }
        const float* git = g_gi_r + (size_t)n * 768;
        float4 h1 = *reinterpret_cast<const float4*>(cur + lane * 4);
        float4 h2 = *reinterpret_cast<const float4*>(cur + 128 + lane * 4);
#pragma unroll 2
        for (int jj = 0; jj < 16; jj++) {
            int j = j0 + jj;
            const float4* r0 = reinterpret_cast<const float4*>(Whh + (size_t)j * HRR);
            const float4* r1 = reinterpret_cast<const float4*>(Whh + (size_t)(j + 256) * HRR);
            const float4* r2 = reinterpret_cast<const float4*>(Whh + (size_t)(j + 512) * HRR);
            float4 a = __ldg(r0 + lane), c = __ldg(r0 + 32 + lane);
            float s0 = a.x * h1.x + a.y * h1.y + a.z * h1.z + a.w * h1.w
                     + c.x * h2.x + c.y * h2.y + c.z * h2.z + c.w * h2.w;
            a = __ldg(r1 + lane); c = __ldg(r1 + 32 + lane);
            float s1 = a.x * h1.x + a.y * h1.y + a.z * h1.z + a.w * h1.w
                     + c.x * h2.x + c.y * h2.y + c.z * h2.z + c.w * h2.w;
            a = __ldg(r2 + lane); c = __ldg(r2 + 32 + lane);
            float s2 = a.x * h1.x + a.y * h1.y + a.z * h1.z + a.w * h1.w
                     + c.x * h2.x + c.y * h2.y + c.z * h2.z + c.w * h2.w;
#pragma unroll
            for (int off = 16; off > 0; off >>= 1) {
                s0 += __shfl_xor_sync(0xffffffffu, s0, off);
                s1 += __shfl_xor_sync(0xffffffffu, s1, off);
                s2 += __shfl_xor_sync(0xffffffffu, s2, off);
            }
            if (lane == 0) {
                float r = sigf(git[j] + s0);
                float z = sigf(git[256 + j] + s1);
                float nn2 = tanhfast(git[512 + j] + r * (s2 + __ldg(&bhh[512 + j])));
                float hn = (1.f - z) * nn2 + z * cur[j];
                nxt[j] = hn;
                g_Hr[(size_t)n * HRR + j] = hn;
            }
        }
        __syncthreads();
        float* tmp = cur; cur = nxt; nxt = tmp;
    }
}

// ---------------- fused fat kernel ----------------
__global__ __launch_bounds__(512) void k_fat(
    const float* __restrict__ x,
    const float* __restrict__ r_wih,  const float* __restrict__ r_bih,
    const float* __restrict__ e1_wih, const float* __restrict__ e1_bih,
    const float* __restrict__ e2_wih, const float* __restrict__ e2_bih,
    const float* __restrict__ e3_wih, const float* __restrict__ e3_bih,
    const float* __restrict__ r_whh,  const float* __restrict__ r_bhh,
    const float* __restrict__ e1_whh, const float* __restrict__ e1_bhh,
    const float* __restrict__ e2_whh, const float* __restrict__ e2_bhh,
    const float* __restrict__ e3_whh, const float* __restrict__ e3_bhh)
{
    __shared__ unsigned long long pairs[1024];
    __shared__ float hsm[512];
    __shared__ float As[64][17];
    __shared__ float Ws[64][17];
    const int bid = blockIdx.x;
    const int tid = threadIdx.x;

    if (bid >= 48) {
        // ---------------- GEMM path ----------------
        int gid = bid - 48;
        int mb = gid / 54;
        int r  = gid % 54;
        const float* W; const float* bias; const float* bhh; float* C;
        int Nn, nblk, e, twoH;
        if (r < 12)      { e = 0; nblk = r;      W = r_wih;  bias = r_bih;  bhh = r_bhh;  C = g_gi_r;  Nn = 768;  twoH = 512; }
        else if (r < 18) { e = 1; nblk = r - 12; W = e1_wih; bias = e1_bih; bhh = e1_bhh; C = g_gi_e1; Nn = 384;  twoH = 256; }
        else if (r < 30) { e = 2; nblk = r - 18; W = e2_wih; bias = e2_bih; bhh = e2_bhh; C = g_gi_e2; Nn = 768;  twoH = 512; }
        else             { e = 3; nblk = r - 30; W = e3_wih; bias = e3_bih; bhh = e3_bhh; C = g_gi_e3; Nn = 1536; twoH = 1024; }
        const int m0 = mb * 64, n0 = nblk * 64;
        const int tx = tid & 15, ty = tid >> 4;
        const int lr = tid >> 3, lc = (tid & 7) * 2;

        float acc[2][4];
#pragma unroll
        for (int i = 0; i < 2; i++)
#pragma unroll
            for (int jq = 0; jq < 4; jq++) acc[i][jq] = 0.f;

        for (int kb = 0; kb < 512; kb += 16) {
            float2 av = *reinterpret_cast<const float2*>(&x[(size_t)(m0 + lr) * 512 + kb + lc]);
            float2 wv = *reinterpret_cast<const float2*>(&W[(size_t)(n0 + lr) * 512 + kb + lc]);
            As[lr][lc] = av.x; As[lr][lc + 1] = av.y;
            Ws[lr][lc] = wv.x; Ws[lr][lc + 1] = wv.y;
            __syncthreads();
#pragma unroll
            for (int k = 0; k < 16; k++) {
                float a0 = As[ty * 2][k], a1 = As[ty * 2 + 1][k];
                float b0 = Ws[tx * 4][k], b1 = Ws[tx * 4 + 1][k];
                float b2 = Ws[tx * 4 + 2][k], b3 = Ws[tx * 4 + 3][k];
                acc[0][0] += a0 * b0; acc[0][1] += a0 * b1; acc[0][2] += a0 * b2; acc[0][3] += a0 * b3;
                acc[1][0] += a1 * b0; acc[1][1] += a1 * b1; acc[1][2] += a1 * b2; acc[1][3] += a1 * b3;
            }
            __syncthreads();
        }
#pragma unroll
        for (int i = 0; i < 2; i++)
#pragma unroll
            for (int jq = 0; jq < 4; jq++) {
                int nidx = n0 + tx * 4 + jq;
                float b = __ldg(&bias[nidx]);
                if (nidx < twoH) b += __ldg(&bhh[nidx]);
                C[(size_t)(m0 + ty * 2 + i) * Nn + nidx] = acc[i][jq] + b;
            }
        __syncthreads();
        if (tid == 0) red_rel(&g_girdy[e * 64 + mb]);
        return;
    }

    // ---------------- recurrence path ----------------
    // init ring: consume-side of step 0 is ring[1] with tag 0, value 0 -> zeros OK
    for (int i = tid; i < 1024; i += 512) pairs[i] = 0ull;
    for (int i = tid; i < 512; i += 512) hsm[i] = 0.f;
    for (int i = tid + 512; i < 512; i += 512) {}
    __syncthreads();
    uint32_t paddr = (uint32_t)__cvta_generic_to_shared(pairs);
    const int cid = bid >> 4;
    const int rank = bid & 15;

    if (cid < 2) CLUSTER_SYNC();

    if (cid == 0) {
        expert_recur<512, 16, 2>(rank, 0, e3_whh, e3_bhh, g_gi_e3, g_H3,
                                 g_girdy + 3 * 64, 24, paddr);
    } else if (cid == 1) {
        if (rank < 8)       expert_recur<256, 8, 2>(rank, 0, e2_whh, e2_bhh, g_gi_e2, g_H2,
                                                    g_girdy + 2 * 64, 12, paddr);
        else if (rank < 10) expert_recur<128, 2, 4>(rank - 8, 8, e1_whh, e1_bhh, g_gi_e1, g_H1,
                                                    g_girdy + 1 * 64, 6, paddr);
        else                router_recur(rank - 10, r_whh, r_bhh, g_girdy, 12, hsm, hsm + 256);
    } else {
        if (rank < 10)      router_recur(6 + rank, r_whh, r_bhh, g_girdy, 12, hsm, hsm + 256);
    }

    if (cid < 2) CLUSTER_SYNC();
}

// ---------------- gates ----------------
__global__ void k_gates(const float* __restrict__ rw, const float* __restrict__ rb,
                        const int* __restrict__ task, float* __restrict__ out_raw)
{
    int warp = (blockIdx.x * blockDim.x + threadIdx.x) >> 5;
    int lane = threadIdx.x & 31;
    if (warp >= NN) return;
    const float* h = g_Hr + (size_t)warp * HRR;
    float hr[8];
#pragma unroll
    for (int i = 0; i < 8; i++) hr[i] = fmaxf(h[i * 32 + lane], 0.f);
    float lg[4];
#pragma unroll
    for (int e = 0; e < 4; e++) {
        float s = 0.f;
#pragma unroll
        for (int i = 0; i < 8; i++) s += __ldg(&rw[e * HRR + i * 32 + lane]) * hr[i];
#pragma unroll
        for (int off = 16; off > 0; off >>= 1) s += __shfl_xor_sync(0xffffffffu, s, off);
        lg[e] = s;
    }
    if (lane == 0) {
#pragma unroll
        for (int e = 0; e < 4; e++) lg[e] += __ldg(&rb[e]);
        float mx = fmaxf(fmaxf(lg[0], lg[1]), fmaxf(lg[2], lg[3]));
        float ex[4], se = 0.f;
#pragma unroll
        for (int e = 0; e < 4; e++) { ex[e] = __expf(lg[e] - mx); se += ex[e]; }
        float inv = 1.f / se;
        float gg[4];
#pragma unroll
        for (int e = 0; e < 4; e++) {
            gg[e] = ex[e] * inv;
            out_raw[warp * 4 + e] = gg[e];
            g_gates[warp * 4 + e] = gg[e];
        }
        float eul = gg[1] * 128.f + gg[2] * 256.f + gg[3] * 512.f;
        int tk = task[warp];
        atomicAdd(&g_tsum[tk], eul);
        atomicAdd(&g_tcnt[tk], 1u);
    }
}

// ---------------- BN stats: deterministic two-pass ----------------
__global__ void k_bnp() {
    int bx = blockIdx.x, rc = blockIdx.y, tid = threadIdx.x;
    const float* Hb; int H, c;
    if (bx == 0)      { Hb = g_H1; H = 128; c = tid; }
    else if (bx < 3)  { Hb = g_H2; H = 256; c = (bx - 1) * 128 + tid; }
    else              { Hb = g_H3; H = 512; c = (bx - 3) * 128 + tid; }
    float s = 0.f, s2 = 0.f;
    int n0 = rc * (NN / 8);
#pragma unroll 8
    for (int n = n0; n < n0 + NN / 8; n++) {
        float v = __ldg(&Hb[(size_t)n * H + c]);
        s += v; s2 += v * v;
    }
    g_bnPS [rc][bx * 128 + tid] = s;
    g_bnPS2[rc][bx * 128 + tid] = s2;
}

__global__ void k_bnf(const float* g1, const float* b1, const float* g2, const float* b2,
                      const float* g3, const float* b3)
{
    int bx = blockIdx.x, tid = threadIdx.x;
    int ei, c;
    if (bx == 0)      { ei = 0; c = tid; }
    else if (bx < 3)  { ei = 1; c = (bx - 1) * 128 + tid; }
    else              { ei = 2; c = (bx - 3) * 128 + tid; }
    float s = 0.f, s2 = 0.f;
#pragma unroll
    for (int rc = 0; rc < 8; rc++) { s += g_bnPS[rc][bx * 128 + tid]; s2 += g_bnPS2[rc][bx * 128 + tid]; }
    float mu = s * (1.f / NN);
    float var = s2 * (1.f / NN) - mu * mu;
    const float* gg = (ei == 0) ? g1 : (ei == 1) ? g2 : g3;
    const float* bb = (ei == 0) ? b1 : (ei == 1) ? b2 : b3;
    float A = gg[c] * rsqrtf(var + BN_EPS);
    g_bnA[ei][c] = A;
    g_bnB[ei][c] = bb[c] - mu * A;
}

// ---------------- epilogue ----------------
__global__ __launch_bounds__(256) void k_epi(
    const float* __restrict__ ow, const float* __restrict__ ob,
    const float* __restrict__ x, float* __restrict__ out, int ei, int H)
{
    const float* Hb = (ei == 1) ? g_H1 : (ei == 2) ? g_H2 : g_H3;
    const float* bA = g_bnA[ei - 1];
    const float* bBv = g_bnB[ei - 1];
    __shared__ float As[64][17];
    __shared__ float Ws[64][17];
    const int tid = threadIdx.x;
    const int tx = tid & 15, ty = tid >> 4;
    const int m0 = blockIdx.y * 64, n0 = blockIdx.x * 64;
    const int lr = tid >> 2, lc = (tid & 3) * 4;

    float acc[4][4];
#pragma unroll
    for (int i = 0; i < 4; i++)
#pragma unroll
        for (int j = 0; j < 4; j++) acc[i][j] = 0.f;

    for (int kb = 0; kb < H; kb += 16) {
        float4 av = *reinterpret_cast<const float4*>(&Hb[(size_t)(m0 + lr) * H + kb + lc]);
        float4 wv = *reinterpret_cast<const float4*>(&ow[(size_t)(n0 + lr) * H + kb + lc]);
        As[lr][lc + 0] = fmaxf(av.x * __ldg(&bA[kb + lc + 0]) + __ldg(&bBv[kb + lc + 0]), 0.f);
        As[lr][lc + 1] = fmaxf(av.y * __ldg(&bA[kb + lc + 1]) + __ldg(&bBv[kb + lc + 1]), 0.f);
        As[lr][lc + 2] = fmaxf(av.z * __ldg(&bA[kb + lc + 2]) + __ldg(&bBv[kb + lc + 2]), 0.f);
        As[lr][lc + 3] = fmaxf(av.w * __ldg(&bA[kb + lc + 3]) + __ldg(&bBv[kb + lc + 3]), 0.f);
        Ws[lr][lc + 0] = wv.x; Ws[lr][lc + 1] = wv.y; Ws[lr][lc + 2] = wv.z; Ws[lr][lc + 3] = wv.w;
        __syncthreads();
#pragma unroll
        for (int k = 0; k < 16; k++) {
            float a[4], b[4];
#pragma unroll
            for (int i = 0; i < 4; i++) a[i] = As[ty * 4 + i][k];
#pragma unroll
            for (int j = 0; j < 4; j++) b[j] = Ws[tx * 4 + j][k];
#pragma unroll
            for (int i = 0; i < 4; i++)
#pragma unroll
                for (int j = 0; j < 4; j++) acc[i][j] += a[i] * b[j];
        }
        __syncthreads();
    }
#pragma unroll
    for (int i = 0; i < 4; i++) {
        int m = m0 + ty * 4 + i;
        float gate = g_gates[m * 4 + ei];
        float g0 = g_gates[m * 4];
#pragma unroll
        for (int j = 0; j < 4; j++) {
            int n = n0 + tx * 4 + j;
            float v = (acc[i][j] + __ldg(&ob[n])) * gate;
            if (ei == 1) v += g0 * __ldg(&x[(size_t)m * DD + n]);
            else         v += out[(size_t)m * DD + n];
            out[(size_t)m * DD + n] = v;
        }
    }
}

// ---------------- task losses ----------------
__global__ void k_tl(float* o) {
    int i = threadIdx.x;
    if (i < 4) o[i] = g_tsum[i] / (float)g_tcnt[i];
}

// ---------------- launch ----------------
extern "C" void kernel_launch(void* const* d_in, const int* in_sizes, int n_in,
                              void* d_out, int out_size)
{
    const float* x      = (const float*)d_in[0];
    const int*   task   = (const int*)d_in[1];
    const float* r_wih  = (const float*)d_in[2];
    const float* r_whh  = (const float*)d_in[3];
    const float* r_bih  = (const float*)d_in[4];
    const float* r_bhh  = (const float*)d_in[5];
    const float* r_ow   = (const float*)d_in[6];
    const float* r_ob   = (const float*)d_in[7];
    const float* e1_wih = (const float*)d_in[8];
    const float* e1_whh = (const float*)d_in[9];
    const float* e1_bih = (const float*)d_in[10];
    const float* e1_bhh = (const float*)d_in[11];
    const float* e1_bng = (const float*)d_in[12];
    const float* e1_bnb = (const float*)d_in[13];
    const float* e1_ow  = (const float*)d_in[14];
    const float* e1_ob  = (const float*)d_in[15];
    const float* e2_wih = (const float*)d_in[16];
    const float* e2_whh = (const float*)d_in[17];
    const float* e2_bih = (const float*)d_in[18];
    const float* e2_bhh = (const float*)d_in[19];
    const float* e2_bng = (const float*)d_in[20];
    const float* e2_bnb = (const float*)d_in[21];
    const float* e2_ow  = (const float*)d_in[22];
    const float* e2_ob  = (const float*)d_in[23];
    const float* e3_wih = (const float*)d_in[24];
    const float* e3_whh = (const float*)d_in[25];
    const float* e3_bih = (const float*)d_in[26];
    const float* e3_bhh = (const float*)d_in[27];
    const float* e3_bng = (const float*)d_in[28];
    const float* e3_bnb = (const float*)d_in[29];
    const float* e3_ow  = (const float*)d_in[30];
    const float* e3_ob  = (const float*)d_in[31];

    float* out = (float*)d_out;
    float* raw = out + (size_t)NN * DD;
    float* tl  = raw + (size_t)NN * 4;

    k_zero<<<1, 256>>>();

    cudaFuncSetAttribute(k_fat, cudaFuncAttributeNonPortableClusterSizeAllowed, 1);
    cudaLaunchConfig_t cfg = {};
    cfg.gridDim = dim3(3504, 1, 1);
    cfg.blockDim = dim3(512, 1, 1);
    cfg.dynamicSmemBytes = 0;
    cfg.stream = 0;
    cudaLaunchAttribute lattr[1];
    lattr[0].id = cudaLaunchAttributeClusterDimension;
    lattr[0].val.clusterDim.x = 16;
    lattr[0].val.clusterDim.y = 1;
    lattr[0].val.clusterDim.z = 1;
    cfg.attrs = lattr;
    cfg.numAttrs = 1;
    cudaLaunchKernelEx(&cfg, k_fat,
                       x, r_wih, r_bih, e1_wih, e1_bih, e2_wih, e2_bih, e3_wih, e3_bih,
                       r_whh, r_bhh, e1_whh, e1_bhh, e2_whh, e2_bhh, e3_whh, e3_bhh);

    k_gates<<<512, 256>>>(r_ow, r_ob, task, raw);
    k_bnp<<<dim3(7, 8), 128>>>();
    k_bnf<<<7, 128>>>(e1_bng, e1_bnb, e2_bng, e2_bnb, e3_bng, e3_bnb);
    k_epi<<<dim3(8, 64), 256>>>(e1_ow, e1_ob, x, out, 1, 128);
    k_epi<<<dim3(8, 64), 256>>>(e2_ow, e2_ob, x, out, 2, 256);
    k_epi<<<dim3(8, 64), 256>>>(e3_ow, e3_ob, x, out, 3, 512);
    k_tl<<<1, 32>>>(tl);
}

// round 15
// speedup vs baseline: 5.0462x; 5.0462x over previous
#include <cuda_runtime.h>
#include <stdint.h>
#include <math.h>

#define TT 256
#define BB 16
#define DD 512
#define NN 4096
#define HRR 256
#define BN_EPS 1e-5f

// ---------------- device scratch ----------------
__device__ float g_gi_r [NN * 768];
__device__ float g_gi_e1[NN * 384];
__device__ float g_gi_e2[NN * 768];
__device__ float g_gi_e3[NN * 1536];
__device__ float g_Hr[NN * HRR];
__device__ float g_H1[NN * 128];
__device__ float g_H2[NN * 256];
__device__ float g_H3[NN * 512];
__device__ float g_gates[NN * 4];
__device__ unsigned g_girdy[4 * 64];
__device__ float g_bnPS [32][896];
__device__ float g_bnPS2[32][896];
__device__ float g_bnA[3][512];
__device__ float g_bnB[3][512];
__device__ float g_tsum[4];
__device__ unsigned g_tcnt[4];

__device__ __forceinline__ float sigf(float x) { return 1.f / (1.f + __expf(-x)); }
__device__ __forceinline__ float tanhfast(float x) {
    float xc = fminf(fmaxf(x, -9.f), 9.f);
    float e = __expf(2.f * xc);
    return __fdividef(e - 1.f, e + 1.f);
}
__device__ __forceinline__ unsigned long long fma2(unsigned long long a, unsigned long long b,
                                                   unsigned long long c) {
    unsigned long long d;
    asm("fma.rn.f32x2 %0, %1, %2, %3;" : "=l"(d) : "l"(a), "l"(b), "l"(c));
    return d;
}
__device__ __forceinline__ int padi(int k) { return k + ((k >> 5) << 1); }  // bank-pad

__device__ __forceinline__ void st_pair_cluster(uint32_t laddr, int rank, unsigned long long x) {
    uint32_t ra;
    asm volatile("mapa.shared::cluster.u32 %0, %1, %2;" : "=r"(ra) : "r"(laddr), "r"(rank));
    asm volatile("st.shared::cluster.b64 [%0], %1;" :: "r"(ra), "l"(x) : "memory");
}
__device__ __forceinline__ unsigned long long ld_pair_sh(uint32_t laddr) {
    unsigned long long v;
    asm volatile("ld.volatile.shared.b64 %0, [%1];" : "=l"(v) : "r"(laddr));
    return v;
}
__device__ __forceinline__ unsigned ld_acq(const unsigned* p) {
    unsigned v;
    asm volatile("ld.acquire.gpu.global.u32 %0, [%1];" : "=r"(v) : "l"(p) : "memory");
    return v;
}
__device__ __forceinline__ void red_rel(unsigned* p) {
    asm volatile("red.release.gpu.global.add.u32 [%0], 1;" :: "l"(p) : "memory");
}
#define CLUSTER_SYNC() do { \
    asm volatile("barrier.cluster.arrive.aligned;" ::: "memory"); \
    asm volatile("barrier.cluster.wait.aligned;" ::: "memory"); } while (0)

// ---------------- zero ----------------
__global__ void k_zero() {
    int i = threadIdx.x;
    if (i < 256) g_girdy[i] = 0u;
    if (i < 4) { g_tsum[i] = 0.f; g_tcnt[i] = 0u; }
}

// ---------------- expert recurrence (round-12 proven: staging + 1 bar/step) ----------------
template <int H, int NC, int JW>
__device__ void expert_recur(int cta, int base_rank,
                             const float* __restrict__ Whh, const float* __restrict__ bhh,
                             const float* gi, float* __restrict__ Hbuf,
                             const unsigned* rdy, int nbk,
                             uint32_t pairs_addr, float* hs0, float* hs1)
{
    constexpr int JPC = H / NC;
    constexpr int LPJ = 32 / JW;
    constexpr int KB  = H / LPJ;
    constexpr int KP  = KB / 2;
    const int tid = threadIdx.x, w = tid >> 5, lane = tid & 31;
    const int jj   = lane / LPJ;
    const int linj = lane % LPJ;
    const int j    = cta * JPC + w * JW + jj;
    const int k0   = linj * KB;
    const int pb   = padi(k0);

    unsigned long long wp[3][KP];
#pragma unroll
    for (int g = 0; g < 3; g++)
#pragma unroll
        for (int p = 0; p < KP; p++)
            wp[g][p] = *reinterpret_cast<const unsigned long long*>(
                &Whh[(size_t)(g * H + j) * H + k0 + 2 * p]);
    const float bhn = bhh[2 * H + j];

    float* cur = hs0;
    float* nxt = hs1;

    while (ld_acq(&rdy[0]) < (unsigned)nbk) {}
    int rdyw = 1;
    float gr0 = gi[j], gr1 = gi[H + j], gr2 = gi[2 * H + j];

    for (int t = 0; t < NN; t++) {
        unsigned long long acc[3] = {0ull, 0ull, 0ull};
        const float* hb = cur + pb;
#pragma unroll
        for (int p = 0; p < KP; p++) {
            unsigned long long hp = *reinterpret_cast<const unsigned long long*>(hb + 2 * p);
#pragma unroll
            for (int g = 0; g < 3; g++) acc[g] = fma2(wp[g][p], hp, acc[g]);
        }
        float s[3];
#pragma unroll
        for (int g = 0; g < 3; g++)
            s[g] = __uint_as_float((unsigned)acc[g]) + __uint_as_float((unsigned)(acc[g] >> 32));
#pragma unroll
        for (int off = LPJ / 2; off > 0; off >>= 1)
#pragma unroll
            for (int g = 0; g < 3; g++) s[g] += __shfl_xor_sync(0xffffffffu, s[g], off);

        float r = sigf(gr0 + s[0]);
        float z = sigf(gr1 + s[1]);
        float n = tanhfast(gr2 + r * (s[2] + bhn));
        float hn = (1.f - z) * n + z * cur[padi(j)];

        const int par = t & 1;
        if (linj < NC) {
            unsigned long long x =
                ((unsigned long long)(unsigned)(t + 1) << 32) |
                (unsigned long long)__float_as_uint(hn);
            uint32_t la = pairs_addr + (uint32_t)((par * H + j) * 8);
            st_pair_cluster(la, base_rank + linj, x);
        }
        if (linj == 0) Hbuf[(size_t)t * H + j] = hn;

        {
            int tn = (t + 1 < NN) ? t + 1 : t;
            int blk = tn >> 6;
            if (blk >= rdyw) {
                while (ld_acq(&rdy[blk]) < (unsigned)nbk) {}
                rdyw = blk + 1;
            }
            const float* gin = gi + (size_t)tn * 3 * H;
            gr0 = gin[j]; gr1 = gin[H + j]; gr2 = gin[2 * H + j];
        }
        if (tid < H) {
            uint32_t la = pairs_addr + (uint32_t)((par * H + tid) * 8);
            unsigned long long v;
            do { v = ld_pair_sh(la); } while ((unsigned)(v >> 32) != (unsigned)(t + 1));
            nxt[padi(tid)] = __uint_as_float((unsigned)v);
        }
        __syncthreads();
        float* tmp = cur; cur = nxt; nxt = tmp;
    }
}

// ---------------- router recurrence (+ readiness gating) ----------------
__device__ void router_recur(int b, const float* __restrict__ Whh, const float* __restrict__ bhh,
                             const unsigned* rdy, int nbk, float* cur, float* nxt)
{
    const int tid = threadIdx.x, w = tid >> 5, lane = tid & 31;
    const int j0 = w * 16;
    __syncthreads();
    int rdyw = 0;

    for (int t = 0; t < TT; t++) {
        const int n = t * BB + b;
        int blk = n >> 6;
        if (blk >= rdyw) {
            while (ld_acq(&rdy[blk]) < (unsigned)nbk) {}
            rdyw = blk + 1;
        }
        const float* git = g_gi_r + (size_t)n * 768;
        float4 h1 = *reinterpret_cast<const float4*>(cur + lane * 4);
        float4 h2 = *reinterpret_cast<const float4*>(cur + 128 + lane * 4);
#pragma unroll 2
        for (int jj = 0; jj < 16; jj++) {
            int j = j0 + jj;
            const float4* r0 = reinterpret_cast<const float4*>(Whh + (size_t)j * HRR);
            const float4* r1 = reinterpret_cast<const float4*>(Whh + (size_t)(j + 256) * HRR);
            const float4* r2 = reinterpret_cast<const float4*>(Whh + (size_t)(j + 512) * HRR);
            float4 a = __ldg(r0 + lane), c = __ldg(r0 + 32 + lane);
            float s0 = a.x * h1.x + a.y * h1.y + a.z * h1.z + a.w * h1.w
                     + c.x * h2.x + c.y * h2.y + c.z * h2.z + c.w * h2.w;
            a = __ldg(r1 + lane); c = __ldg(r1 + 32 + lane);
            float s1 = a.x * h1.x + a.y * h1.y + a.z * h1.z + a.w * h1.w
                     + c.x * h2.x + c.y * h2.y + c.z * h2.z + c.w * h2.w;
            a = __ldg(r2 + lane); c = __ldg(r2 + 32 + lane);
            float s2 = a.x * h1.x + a.y * h1.y + a.z * h1.z + a.w * h1.w
                     + c.x * h2.x + c.y * h2.y + c.z * h2.z + c.w * h2.w;
#pragma unroll
            for (int off = 16; off > 0; off >>= 1) {
                s0 += __shfl_xor_sync(0xffffffffu, s0, off);
                s1 += __shfl_xor_sync(0xffffffffu, s1, off);
                s2 += __shfl_xor_sync(0xffffffffu, s2, off);
            }
            if (lane == 0) {
                float r = sigf(git[j] + s0);
                float z = sigf(git[256 + j] + s1);
                float nn2 = tanhfast(git[512 + j] + r * (s2 + __ldg(&bhh[512 + j])));
                float hn = (1.f - z) * nn2 + z * cur[j];
                nxt[j] = hn;
                g_Hr[(size_t)n * HRR + j] = hn;
            }
        }
        __syncthreads();
        float* tmp = cur; cur = nxt; nxt = tmp;
    }
}

// ---------------- fused fat kernel: 48 recurrence CTAs + 3456 GEMM CTAs ----------------
__global__ __launch_bounds__(512) void k_fat(
    const float* __restrict__ x,
    const float* __restrict__ r_wih,  const float* __restrict__ r_bih,
    const float* __restrict__ e1_wih, const float* __restrict__ e1_bih,
    const float* __restrict__ e2_wih, const float* __restrict__ e2_bih,
    const float* __restrict__ e3_wih, const float* __restrict__ e3_bih,
    const float* __restrict__ r_whh,  const float* __restrict__ r_bhh,
    const float* __restrict__ e1_whh, const float* __restrict__ e1_bhh,
    const float* __restrict__ e2_whh, const float* __restrict__ e2_bhh,
    const float* __restrict__ e3_whh, const float* __restrict__ e3_bhh)
{
    __shared__ unsigned long long pairs[1024];
    __shared__ float hsm[1152];
    __shared__ float As[64][17];
    __shared__ float Ws[64][17];
    const int bid = blockIdx.x;
    const int tid = threadIdx.x;

    if (bid >= 48) {
        // ---------------- GEMM path (512 threads, 64x64 tile) ----------------
        int gid = bid - 48;
        int mb = gid / 54;
        int r  = gid % 54;
        const float* W; const float* bias; const float* bhh; float* C;
        int Nn, nblk, e, twoH;
        if (r < 12)      { e = 0; nblk = r;      W = r_wih;  bias = r_bih;  bhh = r_bhh;  C = g_gi_r;  Nn = 768;  twoH = 512; }
        else if (r < 18) { e = 1; nblk = r - 12; W = e1_wih; bias = e1_bih; bhh = e1_bhh; C = g_gi_e1; Nn = 384;  twoH = 256; }
        else if (r < 30) { e = 2; nblk = r - 18; W = e2_wih; bias = e2_bih; bhh = e2_bhh; C = g_gi_e2; Nn = 768;  twoH = 512; }
        else             { e = 3; nblk = r - 30; W = e3_wih; bias = e3_bih; bhh = e3_bhh; C = g_gi_e3; Nn = 1536; twoH = 1024; }
        const int m0 = mb * 64, n0 = nblk * 64;
        const int tx = tid & 15, ty = tid >> 4;
        const int lr = tid >> 3, lc = (tid & 7) * 2;

        float acc[2][4];
#pragma unroll
        for (int i = 0; i < 2; i++)
#pragma unroll
            for (int jq = 0; jq < 4; jq++) acc[i][jq] = 0.f;

        for (int kb = 0; kb < 512; kb += 16) {
            float2 av = *reinterpret_cast<const float2*>(&x[(size_t)(m0 + lr) * 512 + kb + lc]);
            float2 wv = *reinterpret_cast<const float2*>(&W[(size_t)(n0 + lr) * 512 + kb + lc]);
            As[lr][lc] = av.x; As[lr][lc + 1] = av.y;
            Ws[lr][lc] = wv.x; Ws[lr][lc + 1] = wv.y;
            __syncthreads();
#pragma unroll
            for (int k = 0; k < 16; k++) {
                float a0 = As[ty * 2][k], a1 = As[ty * 2 + 1][k];
                float b0 = Ws[tx * 4][k], b1 = Ws[tx * 4 + 1][k];
                float b2 = Ws[tx * 4 + 2][k], b3 = Ws[tx * 4 + 3][k];
                acc[0][0] += a0 * b0; acc[0][1] += a0 * b1; acc[0][2] += a0 * b2; acc[0][3] += a0 * b3;
                acc[1][0] += a1 * b0; acc[1][1] += a1 * b1; acc[1][2] += a1 * b2; acc[1][3] += a1 * b3;
            }
            __syncthreads();
        }
#pragma unroll
        for (int i = 0; i < 2; i++)
#pragma unroll
            for (int jq = 0; jq < 4; jq++) {
                int nidx = n0 + tx * 4 + jq;
                float b = __ldg(&bias[nidx]);
                if (nidx < twoH) b += __ldg(&bhh[nidx]);
                C[(size_t)(m0 + ty * 2 + i) * Nn + nidx] = acc[i][jq] + b;
            }
        __syncthreads();
        if (tid == 0) red_rel(&g_girdy[e * 64 + mb]);
        return;
    }

    // ---------------- recurrence path ----------------
    for (int i = tid; i < 1024; i += 512) pairs[i] = 0ull;
    for (int i = tid; i < 1152; i += 512) hsm[i] = 0.f;
    __syncthreads();
    uint32_t paddr = (uint32_t)__cvta_generic_to_shared(pairs);
    const int cid = bid >> 4;
    const int rank = bid & 15;

    if (cid < 2) CLUSTER_SYNC();

    if (cid == 0) {
        expert_recur<512, 16, 2>(rank, 0, e3_whh, e3_bhh, g_gi_e3, g_H3,
                                 g_girdy + 3 * 64, 24, paddr, hsm, hsm + 576);
    } else if (cid == 1) {
        if (rank < 8)       expert_recur<256, 8, 2>(rank, 0, e2_whh, e2_bhh, g_gi_e2, g_H2,
                                                    g_girdy + 2 * 64, 12, paddr, hsm, hsm + 576);
        else if (rank < 10) expert_recur<128, 2, 4>(rank - 8, 8, e1_whh, e1_bhh, g_gi_e1, g_H1,
                                                    g_girdy + 1 * 64, 6, paddr, hsm, hsm + 576);
        else                router_recur(rank - 10, r_whh, r_bhh, g_girdy, 12, hsm, hsm + 576);
    } else {
        if (rank < 10)      router_recur(6 + rank, r_whh, r_bhh, g_girdy, 12, hsm, hsm + 576);
    }

    if (cid < 2) CLUSTER_SYNC();
}

// ---------------- gates ----------------
__global__ void k_gates(const float* __restrict__ rw, const float* __restrict__ rb,
                        const int* __restrict__ task, float* __restrict__ out_raw)
{
    int warp = (blockIdx.x * blockDim.x + threadIdx.x) >> 5;
    int lane = threadIdx.x & 31;
    if (warp >= NN) return;
    const float* h = g_Hr + (size_t)warp * HRR;
    float hr[8];
#pragma unroll
    for (int i = 0; i < 8; i++) hr[i] = fmaxf(h[i * 32 + lane], 0.f);
    float lg[4];
#pragma unroll
    for (int e = 0; e < 4; e++) {
        float s = 0.f;
#pragma unroll
        for (int i = 0; i < 8; i++) s += __ldg(&rw[e * HRR + i * 32 + lane]) * hr[i];
#pragma unroll
        for (int off = 16; off > 0; off >>= 1) s += __shfl_xor_sync(0xffffffffu, s, off);
        lg[e] = s;
    }
    if (lane == 0) {
#pragma unroll
        for (int e = 0; e < 4; e++) lg[e] += __ldg(&rb[e]);
        float mx = fmaxf(fmaxf(lg[0], lg[1]), fmaxf(lg[2], lg[3]));
        float ex[4], se = 0.f;
#pragma unroll
        for (int e = 0; e < 4; e++) { ex[e] = __expf(lg[e] - mx); se += ex[e]; }
        float inv = 1.f / se;
        float gg[4];
#pragma unroll
        for (int e = 0; e < 4; e++) {
            gg[e] = ex[e] * inv;
            out_raw[warp * 4 + e] = gg[e];
            g_gates[warp * 4 + e] = gg[e];
        }
        float eul = gg[1] * 128.f + gg[2] * 256.f + gg[3] * 512.f;
        int tk = task[warp];
        atomicAdd(&g_tsum[tk], eul);
        atomicAdd(&g_tcnt[tk], 1u);
    }
}

// ---------------- BN stats: deterministic two-pass, 32-way split ----------------
__global__ void k_bnp() {
    int bx = blockIdx.x, rc = blockIdx.y, tid = threadIdx.x;
    const float* Hb; int H, c;
    if (bx == 0)      { Hb = g_H1; H = 128; c = tid; }
    else if (bx < 3)  { Hb = g_H2; H = 256; c = (bx - 1) * 128 + tid; }
    else              { Hb = g_H3; H = 512; c = (bx - 3) * 128 + tid; }
    float s = 0.f, s2 = 0.f;
    int n0 = rc * (NN / 32);
#pragma unroll 8
    for (int n = n0; n < n0 + NN / 32; n++) {
        float v = __ldg(&Hb[(size_t)n * H + c]);
        s += v; s2 += v * v;
    }
    g_bnPS [rc][bx * 128 + tid] = s;
    g_bnPS2[rc][bx * 128 + tid] = s2;
}

__global__ void k_bnf(const float* g1, const float* b1, const float* g2, const float* b2,
                      const float* g3, const float* b3)
{
    int bx = blockIdx.x, tid = threadIdx.x;
    int ei, c;
    if (bx == 0)      { ei = 0; c = tid; }
    else if (bx < 3)  { ei = 1; c = (bx - 1) * 128 + tid; }
    else              { ei = 2; c = (bx - 3) * 128 + tid; }
    float s = 0.f, s2 = 0.f;
#pragma unroll
    for (int rc = 0; rc < 32; rc++) { s += g_bnPS[rc][bx * 128 + tid]; s2 += g_bnPS2[rc][bx * 128 + tid]; }
    float mu = s * (1.f / NN);
    float var = s2 * (1.f / NN) - mu * mu;
    const float* gg = (ei == 0) ? g1 : (ei == 1) ? g2 : g3;
    const float* bb = (ei == 0) ? b1 : (ei == 1) ? b2 : b3;
    float A = gg[c] * rsqrtf(var + BN_EPS);
    g_bnA[ei][c] = A;
    g_bnB[ei][c] = bb[c] - mu * A;
}

// ---------------- fused epilogue: out = g0*x + sum_e gate_e*(relu(bn(H_e))@ow_e^T + ob_e) ----------------
__global__ __launch_bounds__(256) void k_epi_all(
    const float* __restrict__ ow1, const float* __restrict__ ob1,
    const float* __restrict__ ow2, const float* __restrict__ ob2,
    const float* __restrict__ ow3, const float* __restrict__ ob3,
    const float* __restrict__ x, float* __restrict__ out)
{
    __shared__ float As[64][17];
    __shared__ float Ws[64][17];
    const int tid = threadIdx.x;
    const int tx = tid & 15, ty = tid >> 4;
    const int m0 = blockIdx.y * 64, n0 = blockIdx.x * 64;
    const int lr = tid >> 2, lc = (tid & 3) * 4;

    float tot[4][4];
#pragma unroll
    for (int i = 0; i < 4; i++) {
        int m = m0 + ty * 4 + i;
        float g0 = g_gates[m * 4];
#pragma unroll
        for (int j = 0; j < 4; j++)
            tot[i][j] = g0 * __ldg(&x[(size_t)m * DD + n0 + tx * 4 + j]);
    }

    for (int s = 0; s < 3; s++) {
        const float* Hb = (s == 0) ? g_H1 : (s == 1) ? g_H2 : g_H3;
        const float* ow = (s == 0) ? ow1 : (s == 1) ? ow2 : ow3;
        const float* ob = (s == 0) ? ob1 : (s == 1) ? ob2 : ob3;
        const int H = (s == 0) ? 128 : (s == 1) ? 256 : 512;
        const float* bA = g_bnA[s];
        const float* bBv = g_bnB[s];

        float acc[4][4];
#pragma unroll
        for (int i = 0; i < 4; i++)
#pragma unroll
            for (int j = 0; j < 4; j++) acc[i][j] = 0.f;

        for (int kb = 0; kb < H; kb += 16) {
            float4 av = *reinterpret_cast<const float4*>(&Hb[(size_t)(m0 + lr) * H + kb + lc]);
            float4 wv = *reinterpret_cast<const float4*>(&ow[(size_t)(n0 + lr) * H + kb + lc]);
            As[lr][lc + 0] = fmaxf(av.x * __ldg(&bA[kb + lc + 0]) + __ldg(&bBv[kb + lc + 0]), 0.f);
            As[lr][lc + 1] = fmaxf(av.y * __ldg(&bA[kb + lc + 1]) + __ldg(&bBv[kb + lc + 1]), 0.f);
            As[lr][lc + 2] = fmaxf(av.z * __ldg(&bA[kb + lc + 2]) + __ldg(&bBv[kb + lc + 2]), 0.f);
            As[lr][lc + 3] = fmaxf(av.w * __ldg(&bA[kb + lc + 3]) + __ldg(&bBv[kb + lc + 3]), 0.f);
            Ws[lr][lc + 0] = wv.x; Ws[lr][lc + 1] = wv.y; Ws[lr][lc + 2] = wv.z; Ws[lr][lc + 3] = wv.w;
            __syncthreads();
#pragma unroll
            for (int k = 0; k < 16; k++) {
                float a[4], b[4];
#pragma unroll
                for (int i = 0; i < 4; i++) a[i] = As[ty * 4 + i][k];
#pragma unroll
                for (int j = 0; j < 4; j++) b[j] = Ws[tx * 4 + j][k];
#pragma unroll
                for (int i = 0; i < 4; i++)
#pragma unroll
                    for (int j = 0; j < 4; j++) acc[i][j] += a[i] * b[j];
            }
            __syncthreads();
        }
#pragma unroll
        for (int i = 0; i < 4; i++) {
            int m = m0 + ty * 4 + i;
            float gate = g_gates[m * 4 + s + 1];
#pragma unroll
            for (int j = 0; j < 4; j++)
                tot[i][j] += gate * (acc[i][j] + __ldg(&ob[n0 + tx * 4 + j]));
        }
    }

#pragma unroll
    for (int i = 0; i < 4; i++) {
        int m = m0 + ty * 4 + i;
#pragma unroll
        for (int j = 0; j < 4; j++)
            out[(size_t)m * DD + n0 + tx * 4 + j] = tot[i][j];
    }
}

// ---------------- task losses ----------------
__global__ void k_tl(float* o) {
    int i = threadIdx.x;
    if (i < 4) o[i] = g_tsum[i] / (float)g_tcnt[i];
}

// ---------------- launch ----------------
extern "C" void kernel_launch(void* const* d_in, const int* in_sizes, int n_in,
                              void* d_out, int out_size)
{
    const float* x      = (const float*)d_in[0];
    const int*   task   = (const int*)d_in[1];
    const float* r_wih  = (const float*)d_in[2];
    const float* r_whh  = (const float*)d_in[3];
    const float* r_bih  = (const float*)d_in[4];
    const float* r_bhh  = (const float*)d_in[5];
    const float* r_ow   = (const float*)d_in[6];
    const float* r_ob   = (const float*)d_in[7];
    const float* e1_wih = (const float*)d_in[8];
    const float* e1_whh = (const float*)d_in[9];
    const float* e1_bih = (const float*)d_in[10];
    const float* e1_bhh = (const float*)d_in[11];
    const float* e1_bng = (const float*)d_in[12];
    const float* e1_bnb = (const float*)d_in[13];
    const float* e1_ow  = (const float*)d_in[14];
    const float* e1_ob  = (const float*)d_in[15];
    const float* e2_wih = (const float*)d_in[16];
    const float* e2_whh = (const float*)d_in[17];
    const float* e2_bih = (const float*)d_in[18];
    const float* e2_bhh = (const float*)d_in[19];
    const float* e2_bng = (const float*)d_in[20];
    const float* e2_bnb = (const float*)d_in[21];
    const float* e2_ow  = (const float*)d_in[22];
    const float* e2_ob  = (const float*)d_in[23];
    const float* e3_wih = (const float*)d_in[24];
    const float* e3_whh = (const float*)d_in[25];
    const float* e3_bih = (const float*)d_in[26];
    const float* e3_bhh = (const float*)d_in[27];
    const float* e3_bng = (const float*)d_in[28];
    const float* e3_bnb = (const float*)d_in[29];
    const float* e3_ow  = (const float*)d_in[30];
    const float* e3_ob  = (const float*)d_in[31];

    float* out = (float*)d_out;
    float* raw = out + (size_t)NN * DD;
    float* tl  = raw + (size_t)NN * 4;

    k_zero<<<1, 256>>>();

    cudaFuncSetAttribute(k_fat, cudaFuncAttributeNonPortableClusterSizeAllowed, 1);
    cudaLaunchConfig_t cfg = {};
    cfg.gridDim = dim3(3504, 1, 1);
    cfg.blockDim = dim3(512, 1, 1);
    cfg.dynamicSmemBytes = 0;
    cfg.stream = 0;
    cudaLaunchAttribute lattr[1];
    lattr[0].id = cudaLaunchAttributeClusterDimension;
    lattr[0].val.clusterDim.x = 16;
    lattr[0].val.clusterDim.y = 1;
    lattr[0].val.clusterDim.z = 1;
    cfg.attrs = lattr;
    cfg.numAttrs = 1;
    cudaLaunchKernelEx(&cfg, k_fat,
                       x, r_wih, r_bih, e1_wih, e1_bih, e2_wih, e2_bih, e3_wih, e3_bih,
                       r_whh, r_bhh, e1_whh, e1_bhh, e2_whh, e2_bhh, e3_whh, e3_bhh);

    k_gates<<<512, 256>>>(r_ow, r_ob, task, raw);
    k_bnp<<<dim3(7, 32), 128>>>();
    k_bnf<<<7, 128>>>(e1_bng, e1_bnb, e2_bng, e2_bnb, e3_bng, e3_bnb);
    k_epi_all<<<dim3(8, 64), 256>>>(e1_ow, e1_ob, e2_ow, e2_ob, e3_ow, e3_ob, x, out);
    k_tl<<<1, 32>>>(tl);
}

// round 16
// speedup vs baseline: 5.0739x; 1.0055x over previous
#include <cuda_runtime.h>
#include <stdint.h>
#include <math.h>

#define TT 256
#define BB 16
#define DD 512
#define NN 4096
#define HRR 256
#define BN_EPS 1e-5f

// ---------------- device scratch ----------------
__device__ float g_gi_r [NN * 768];
__device__ float g_gi_e1[NN * 384];
__device__ float g_gi_e2[NN * 768];
__device__ float g_gi_e3[NN * 1536];
__device__ float g_Hr[NN * HRR];
__device__ float g_H1[NN * 128];
__device__ float g_H2[NN * 256];
__device__ float g_H3[NN * 512];
__device__ float g_gates[NN * 4];
__device__ unsigned g_girdy[4 * 64];
__device__ float g_bnPS [32][896];
__device__ float g_bnPS2[32][896];
__device__ float g_bnA[3][512];
__device__ float g_bnB[3][512];
__device__ float g_tsum[4];
__device__ unsigned g_tcnt[4];

__device__ __forceinline__ float sigf(float x) { return 1.f / (1.f + __expf(-x)); }
__device__ __forceinline__ float tanhfast(float x) {
    float xc = fminf(fmaxf(x, -9.f), 9.f);
    float e = __expf(2.f * xc);
    return __fdividef(e - 1.f, e + 1.f);
}
__device__ __forceinline__ unsigned long long fma2(unsigned long long a, unsigned long long b,
                                                   unsigned long long c) {
    unsigned long long d;
    asm("fma.rn.f32x2 %0, %1, %2, %3;" : "=l"(d) : "l"(a), "l"(b), "l"(c));
    return d;
}
__device__ __forceinline__ int padi(int k) { return k + ((k >> 5) << 1); }  // bank-pad

__device__ __forceinline__ void st_pair_cluster(uint32_t laddr, int rank, unsigned long long x) {
    uint32_t ra;
    asm volatile("mapa.shared::cluster.u32 %0, %1, %2;" : "=r"(ra) : "r"(laddr), "r"(rank));
    asm volatile("st.shared::cluster.b64 [%0], %1;" :: "r"(ra), "l"(x) : "memory");
}
__device__ __forceinline__ unsigned long long ld_pair_sh(uint32_t laddr) {
    unsigned long long v;
    asm volatile("ld.volatile.shared.b64 %0, [%1];" : "=l"(v) : "r"(laddr));
    return v;
}
__device__ __forceinline__ unsigned ld_acq(const unsigned* p) {
    unsigned v;
    asm volatile("ld.acquire.gpu.global.u32 %0, [%1];" : "=r"(v) : "l"(p) : "memory");
    return v;
}
__device__ __forceinline__ void red_rel(unsigned* p) {
    asm volatile("red.release.gpu.global.add.u32 [%0], 1;" :: "l"(p) : "memory");
}
#define CLUSTER_SYNC() do { \
    asm volatile("barrier.cluster.arrive.aligned;" ::: "memory"); \
    asm volatile("barrier.cluster.wait.aligned;" ::: "memory"); } while (0)

// ---------------- zero ----------------
__global__ void k_zero() {
    int i = threadIdx.x;
    if (i < 256) g_girdy[i] = 0u;
    if (i < 4) { g_tsum[i] = 0.f; g_tcnt[i] = 0u; }
}

// ---------------- expert recurrence (round-12 proven: staging + 1 bar/step) ----------------
template <int H, int NC, int JW>
__device__ void expert_recur(int cta, int base_rank,
                             const float* __restrict__ Whh, const float* __restrict__ bhh,
                             const float* gi, float* __restrict__ Hbuf,
                             const unsigned* rdy, int nbk,
                             uint32_t pairs_addr, float* hs0, float* hs1)
{
    constexpr int JPC = H / NC;
    constexpr int LPJ = 32 / JW;
    constexpr int KB  = H / LPJ;
    constexpr int KP  = KB / 2;
    const int tid = threadIdx.x, w = tid >> 5, lane = tid & 31;
    const int jj   = lane / LPJ;
    const int linj = lane % LPJ;
    const int j    = cta * JPC + w * JW + jj;
    const int k0   = linj * KB;
    const int pb   = padi(k0);

    unsigned long long wp[3][KP];
#pragma unroll
    for (int g = 0; g < 3; g++)
#pragma unroll
        for (int p = 0; p < KP; p++)
            wp[g][p] = *reinterpret_cast<const unsigned long long*>(
                &Whh[(size_t)(g * H + j) * H + k0 + 2 * p]);
    const float bhn = bhh[2 * H + j];

    float* cur = hs0;
    float* nxt = hs1;

    while (ld_acq(&rdy[0]) < (unsigned)nbk) {}
    int rdyw = 1;
    float gr0 = gi[j], gr1 = gi[H + j], gr2 = gi[2 * H + j];

    for (int t = 0; t < NN; t++) {
        unsigned long long acc[3] = {0ull, 0ull, 0ull};
        const float* hb = cur + pb;
#pragma unroll
        for (int p = 0; p < KP; p++) {
            unsigned long long hp = *reinterpret_cast<const unsigned long long*>(hb + 2 * p);
#pragma unroll
            for (int g = 0; g < 3; g++) acc[g] = fma2(wp[g][p], hp, acc[g]);
        }
        float s[3];
#pragma unroll
        for (int g = 0; g < 3; g++)
            s[g] = __uint_as_float((unsigned)acc[g]) + __uint_as_float((unsigned)(acc[g] >> 32));
#pragma unroll
        for (int off = LPJ / 2; off > 0; off >>= 1)
#pragma unroll
            for (int g = 0; g < 3; g++) s[g] += __shfl_xor_sync(0xffffffffu, s[g], off);

        float r = sigf(gr0 + s[0]);
        float z = sigf(gr1 + s[1]);
        float n = tanhfast(gr2 + r * (s[2] + bhn));
        float hn = (1.f - z) * n + z * cur[padi(j)];

        const int par = t & 1;
        if (linj < NC) {
            unsigned long long x =
                ((unsigned long long)(unsigned)(t + 1) << 32) |
                (unsigned long long)__float_as_uint(hn);
            uint32_t la = pairs_addr + (uint32_t)((par * H + j) * 8);
            st_pair_cluster(la, base_rank + linj, x);
        }
        if (linj == 0) Hbuf[(size_t)t * H + j] = hn;

        {
            int tn = (t + 1 < NN) ? t + 1 : t;
            int blk = tn >> 6;
            if (blk >= rdyw) {
                while (ld_acq(&rdy[blk]) < (unsigned)nbk) {}
                rdyw = blk + 1;
            }
            const float* gin = gi + (size_t)tn * 3 * H;
            gr0 = gin[j]; gr1 = gin[H + j]; gr2 = gin[2 * H + j];
        }
        if (tid < H) {
            uint32_t la = pairs_addr + (uint32_t)((par * H + tid) * 8);
            unsigned long long v;
            do { v = ld_pair_sh(la); } while ((unsigned)(v >> 32) != (unsigned)(t + 1));
            nxt[padi(tid)] = __uint_as_float((unsigned)v);
        }
        __syncthreads();
        float* tmp = cur; cur = nxt; nxt = tmp;
    }
}

// ---------------- router recurrence (+ readiness gating) ----------------
__device__ void router_recur(int b, const float* __restrict__ Whh, const float* __restrict__ bhh,
                             const unsigned* rdy, int nbk, float* cur, float* nxt)
{
    const int tid = threadIdx.x, w = tid >> 5, lane = tid & 31;
    const int j0 = w * 16;
    __syncthreads();
    int rdyw = 0;

    for (int t = 0; t < TT; t++) {
        const int n = t * BB + b;
        int blk = n >> 6;
        if (blk >= rdyw) {
            while (ld_acq(&rdy[blk]) < (unsigned)nbk) {}
            rdyw = blk + 1;
        }
        const float* git = g_gi_r + (size_t)n * 768;
        float4 h1 = *reinterpret_cast<const float4*>(cur + lane * 4);
        float4 h2 = *reinterpret_cast<const float4*>(cur + 128 + lane * 4);
#pragma unroll 2
        for (int jj = 0; jj < 16; jj++) {
            int j = j0 + jj;
            const float4* r0 = reinterpret_cast<const float4*>(Whh + (size_t)j * HRR);
            const float4* r1 = reinterpret_cast<const float4*>(Whh + (size_t)(j + 256) * HRR);
            const float4* r2 = reinterpret_cast<const float4*>(Whh + (size_t)(j + 512) * HRR);
            float4 a = __ldg(r0 + lane), c = __ldg(r0 + 32 + lane);
            float s0 = a.x * h1.x + a.y * h1.y + a.z * h1.z + a.w * h1.w
                     + c.x * h2.x + c.y * h2.y + c.z * h2.z + c.w * h2.w;
            a = __ldg(r1 + lane); c = __ldg(r1 + 32 + lane);
            float s1 = a.x * h1.x + a.y * h1.y + a.z * h1.z + a.w * h1.w
                     + c.x * h2.x + c.y * h2.y + c.z * h2.z + c.w * h2.w;
            a = __ldg(r2 + lane); c = __ldg(r2 + 32 + lane);
            float s2 = a.x * h1.x + a.y * h1.y + a.z * h1.z + a.w * h1.w
                     + c.x * h2.x + c.y * h2.y + c.z * h2.z + c.w * h2.w;
#pragma unroll
            for (int off = 16; off > 0; off >>= 1) {
                s0 += __shfl_xor_sync(0xffffffffu, s0, off);
                s1 += __shfl_xor_sync(0xffffffffu, s1, off);
                s2 += __shfl_xor_sync(0xffffffffu, s2, off);
            }
            if (lane == 0) {
                float r = sigf(git[j] + s0);
                float z = sigf(git[256 + j] + s1);
                float nn2 = tanhfast(git[512 + j] + r * (s2 + __ldg(&bhh[512 + j])));
                float hn = (1.f - z) * nn2 + z * cur[j];
                nxt[j] = hn;
                g_Hr[(size_t)n * HRR + j] = hn;
            }
        }
        __syncthreads();
        float* tmp = cur; cur = nxt; nxt = tmp;
    }
}

// ---------------- fused fat kernel: 48 recurrence CTAs + 3456 GEMM CTAs ----------------
__global__ __launch_bounds__(512) void k_fat(
    const float* __restrict__ x,
    const float* __restrict__ r_wih,  const float* __restrict__ r_bih,
    const float* __restrict__ e1_wih, const float* __restrict__ e1_bih,
    const float* __restrict__ e2_wih, const float* __restrict__ e2_bih,
    const float* __restrict__ e3_wih, const float* __restrict__ e3_bih,
    const float* __restrict__ r_whh,  const float* __restrict__ r_bhh,
    const float* __restrict__ e1_whh, const float* __restrict__ e1_bhh,
    const float* __restrict__ e2_whh, const float* __restrict__ e2_bhh,
    const float* __restrict__ e3_whh, const float* __restrict__ e3_bhh)
{
    __shared__ unsigned long long pairs[1024];
    __shared__ float hsm[1152];
    __shared__ float As[64][17];
    __shared__ float Ws[64][17];
    const int bid = blockIdx.x;
    const int tid = threadIdx.x;

    if (bid >= 48) {
        int gid = bid - 48;
        int mb = gid / 54;
        int r  = gid % 54;
        const float* W; const float* bias; const float* bhh; float* C;
        int Nn, nblk, e, twoH;
        if (r < 12)      { e = 0; nblk = r;      W = r_wih;  bias = r_bih;  bhh = r_bhh;  C = g_gi_r;  Nn = 768;  twoH = 512; }
        else if (r < 18) { e = 1; nblk = r - 12; W = e1_wih; bias = e1_bih; bhh = e1_bhh; C = g_gi_e1; Nn = 384;  twoH = 256; }
        else if (r < 30) { e = 2; nblk = r - 18; W = e2_wih; bias = e2_bih; bhh = e2_bhh; C = g_gi_e2; Nn = 768;  twoH = 512; }
        else             { e = 3; nblk = r - 30; W = e3_wih; bias = e3_bih; bhh = e3_bhh; C = g_gi_e3; Nn = 1536; twoH = 1024; }
        const int m0 = mb * 64, n0 = nblk * 64;
        const int tx = tid & 15, ty = tid >> 4;
        const int lr = tid >> 3, lc = (tid & 7) * 2;

        float acc[2][4];
#pragma unroll
        for (int i = 0; i < 2; i++)
#pragma unroll
            for (int jq = 0; jq < 4; jq++) acc[i][jq] = 0.f;

        for (int kb = 0; kb < 512; kb += 16) {
            float2 av = *reinterpret_cast<const float2*>(&x[(size_t)(m0 + lr) * 512 + kb + lc]);
            float2 wv = *reinterpret_cast<const float2*>(&W[(size_t)(n0 + lr) * 512 + kb + lc]);
            As[lr][lc] = av.x; As[lr][lc + 1] = av.y;
            Ws[lr][lc] = wv.x; Ws[lr][lc + 1] = wv.y;
            __syncthreads();
#pragma unroll
            for (int k = 0; k < 16; k++) {
                float a0 = As[ty * 2][k], a1 = As[ty * 2 + 1][k];
                float b0 = Ws[tx * 4][k], b1 = Ws[tx * 4 + 1][k];
                float b2 = Ws[tx * 4 + 2][k], b3 = Ws[tx * 4 + 3][k];
                acc[0][0] += a0 * b0; acc[0][1] += a0 * b1; acc[0][2] += a0 * b2; acc[0][3] += a0 * b3;
                acc[1][0] += a1 * b0; acc[1][1] += a1 * b1; acc[1][2] += a1 * b2; acc[1][3] += a1 * b3;
            }
            __syncthreads();
        }
#pragma unroll
        for (int i = 0; i < 2; i++)
#pragma unroll
            for (int jq = 0; jq < 4; jq++) {
                int nidx = n0 + tx * 4 + jq;
                float b = __ldg(&bias[nidx]);
                if (nidx < twoH) b += __ldg(&bhh[nidx]);
                C[(size_t)(m0 + ty * 2 + i) * Nn + nidx] = acc[i][jq] + b;
            }
        __syncthreads();
        if (tid == 0) red_rel(&g_girdy[e * 64 + mb]);
        return;
    }

    for (int i = tid; i < 1024; i += 512) pairs[i] = 0ull;
    for (int i = tid; i < 1152; i += 512) hsm[i] = 0.f;
    __syncthreads();
    uint32_t paddr = (uint32_t)__cvta_generic_to_shared(pairs);
    const int cid = bid >> 4;
    const int rank = bid & 15;

    if (cid < 2) CLUSTER_SYNC();

    if (cid == 0) {
        expert_recur<512, 16, 2>(rank, 0, e3_whh, e3_bhh, g_gi_e3, g_H3,
                                 g_girdy + 3 * 64, 24, paddr, hsm, hsm + 576);
    } else if (cid == 1) {
        if (rank < 8)       expert_recur<256, 8, 2>(rank, 0, e2_whh, e2_bhh, g_gi_e2, g_H2,
                                                    g_girdy + 2 * 64, 12, paddr, hsm, hsm + 576);
        else if (rank < 10) expert_recur<128, 2, 4>(rank - 8, 8, e1_whh, e1_bhh, g_gi_e1, g_H1,
                                                    g_girdy + 1 * 64, 6, paddr, hsm, hsm + 576);
        else                router_recur(rank - 10, r_whh, r_bhh, g_girdy, 12, hsm, hsm + 576);
    } else {
        if (rank < 10)      router_recur(6 + rank, r_whh, r_bhh, g_girdy, 12, hsm, hsm + 576);
    }

    if (cid < 2) CLUSTER_SYNC();
}

// ---------------- post1: gates (blocks 0..511) + BN partials (blocks 512..735) ----------------
__global__ __launch_bounds__(256) void k_post1(const float* __restrict__ rw,
                                               const float* __restrict__ rb,
                                               const int* __restrict__ task,
                                               float* __restrict__ out_raw)
{
    const int blk = blockIdx.x;
    const int tid = threadIdx.x;

    if (blk >= 512) {
        // BN partial sums: idx -> (bx in 0..6, rc in 0..31), threads 0..127 active
        if (tid >= 128) return;
        int idx = blk - 512;
        int bx = idx / 32, rc = idx % 32;
        const float* Hb; int H, c;
        if (bx == 0)      { Hb = g_H1; H = 128; c = tid; }
        else if (bx < 3)  { Hb = g_H2; H = 256; c = (bx - 1) * 128 + tid; }
        else              { Hb = g_H3; H = 512; c = (bx - 3) * 128 + tid; }
        float s = 0.f, s2 = 0.f;
        int n0 = rc * (NN / 32);
#pragma unroll 8
        for (int n = n0; n < n0 + NN / 32; n++) {
            float v = __ldg(&Hb[(size_t)n * H + c]);
            s += v; s2 += v * v;
        }
        g_bnPS [rc][bx * 128 + tid] = s;
        g_bnPS2[rc][bx * 128 + tid] = s2;
        return;
    }

    // gates
    int warp = (blk * 256 + tid) >> 5;
    int lane = tid & 31;
    if (warp >= NN) return;
    const float* h = g_Hr + (size_t)warp * HRR;
    float hr[8];
#pragma unroll
    for (int i = 0; i < 8; i++) hr[i] = fmaxf(h[i * 32 + lane], 0.f);
    float lg[4];
#pragma unroll
    for (int e = 0; e < 4; e++) {
        float s = 0.f;
#pragma unroll
        for (int i = 0; i < 8; i++) s += __ldg(&rw[e * HRR + i * 32 + lane]) * hr[i];
#pragma unroll
        for (int off = 16; off > 0; off >>= 1) s += __shfl_xor_sync(0xffffffffu, s, off);
        lg[e] = s;
    }
    if (lane == 0) {
#pragma unroll
        for (int e = 0; e < 4; e++) lg[e] += __ldg(&rb[e]);
        float mx = fmaxf(fmaxf(lg[0], lg[1]), fmaxf(lg[2], lg[3]));
        float ex[4], se = 0.f;
#pragma unroll
        for (int e = 0; e < 4; e++) { ex[e] = __expf(lg[e] - mx); se += ex[e]; }
        float inv = 1.f / se;
        float gg[4];
#pragma unroll
        for (int e = 0; e < 4; e++) {
            gg[e] = ex[e] * inv;
            out_raw[warp * 4 + e] = gg[e];
            g_gates[warp * 4 + e] = gg[e];
        }
        float eul = gg[1] * 128.f + gg[2] * 256.f + gg[3] * 512.f;
        int tk = task[warp];
        atomicAdd(&g_tsum[tk], eul);
        atomicAdd(&g_tcnt[tk], 1u);
    }
}

// ---------------- post2: BN finalize (blocks 0..6) + task losses (block 7) ----------------
__global__ void k_post2(const float* g1, const float* b1, const float* g2, const float* b2,
                        const float* g3, const float* b3, float* tlo)
{
    int bx = blockIdx.x, tid = threadIdx.x;
    if (bx == 7) {
        if (tid < 4) tlo[tid] = g_tsum[tid] / (float)g_tcnt[tid];
        return;
    }
    int ei, c;
    if (bx == 0)      { ei = 0; c = tid; }
    else if (bx < 3)  { ei = 1; c = (bx - 1) * 128 + tid; }
    else              { ei = 2; c = (bx - 3) * 128 + tid; }
    float s = 0.f, s2 = 0.f;
#pragma unroll
    for (int rc = 0; rc < 32; rc++) { s += g_bnPS[rc][bx * 128 + tid]; s2 += g_bnPS2[rc][bx * 128 + tid]; }
    float mu = s * (1.f / NN);
    float var = s2 * (1.f / NN) - mu * mu;
    const float* gg = (ei == 0) ? g1 : (ei == 1) ? g2 : g3;
    const float* bb = (ei == 0) ? b1 : (ei == 1) ? b2 : b3;
    float A = gg[c] * rsqrtf(var + BN_EPS);
    g_bnA[ei][c] = A;
    g_bnB[ei][c] = bb[c] - mu * A;
}

// ---------------- fused epilogue: 128x64 tiles, 8x4 register blocking ----------------
__global__ __launch_bounds__(256) void k_epi_all(
    const float* __restrict__ ow1, const float* __restrict__ ob1,
    const float* __restrict__ ow2, const float* __restrict__ ob2,
    const float* __restrict__ ow3, const float* __restrict__ ob3,
    const float* __restrict__ x, float* __restrict__ out)
{
    __shared__ float As[128][17];
    __shared__ float Ws[64][17];
    const int tid = threadIdx.x;
    const int tx = tid & 15, ty = tid >> 4;         // ty: 8-row group, tx: 4-col group
    const int m0 = blockIdx.y * 128, n0 = blockIdx.x * 64;
    const int lrA = tid >> 1, lcA = (tid & 1) * 8;  // As loads: 8 floats/thread
    const int lrW = tid >> 2, lcW = (tid & 3) * 4;  // Ws loads: 4 floats/thread

    float tot[8][4];
#pragma unroll
    for (int i = 0; i < 8; i++) {
        int m = m0 + ty * 8 + i;
        float g0 = g_gates[m * 4];
#pragma unroll
        for (int j = 0; j < 4; j++)
            tot[i][j] = g0 * __ldg(&x[(size_t)m * DD + n0 + tx * 4 + j]);
    }

    for (int s = 0; s < 3; s++) {
        const float* Hb = (s == 0) ? g_H1 : (s == 1) ? g_H2 : g_H3;
        const float* ow = (s == 0) ? ow1 : (s == 1) ? ow2 : ow3;
        const float* ob = (s == 0) ? ob1 : (s == 1) ? ob2 : ob3;
        const int H = (s == 0) ? 128 : (s == 1) ? 256 : 512;
        const float* bA = g_bnA[s];
        const float* bBv = g_bnB[s];

        float acc[8][4];
#pragma unroll
        for (int i = 0; i < 8; i++)
#pragma unroll
            for (int j = 0; j < 4; j++) acc[i][j] = 0.f;

        for (int kb = 0; kb < H; kb += 16) {
            float4 a1 = *reinterpret_cast<const float4*>(&Hb[(size_t)(m0 + lrA) * H + kb + lcA]);
            float4 a2 = *reinterpret_cast<const float4*>(&Hb[(size_t)(m0 + lrA) * H + kb + lcA + 4]);
            float4 wv = *reinterpret_cast<const float4*>(&ow[(size_t)(n0 + lrW) * H + kb + lcW]);
            As[lrA][lcA + 0] = fmaxf(a1.x * __ldg(&bA[kb + lcA + 0]) + __ldg(&bBv[kb + lcA + 0]), 0.f);
            As[lrA][lcA + 1] = fmaxf(a1.y * __ldg(&bA[kb + lcA + 1]) + __ldg(&bBv[kb + lcA + 1]), 0.f);
            As[lrA][lcA + 2] = fmaxf(a1.z * __ldg(&bA[kb + lcA + 2]) + __ldg(&bBv[kb + lcA + 2]), 0.f);
            As[lrA][lcA + 3] = fmaxf(a1.w * __ldg(&bA[kb + lcA + 3]) + __ldg(&bBv[kb + lcA + 3]), 0.f);
            As[lrA][lcA + 4] = fmaxf(a2.x * __ldg(&bA[kb + lcA + 4]) + __ldg(&bBv[kb + lcA + 4]), 0.f);
            As[lrA][lcA + 5] = fmaxf(a2.y * __ldg(&bA[kb + lcA + 5]) + __ldg(&bBv[kb + lcA + 5]), 0.f);
            As[lrA][lcA + 6] = fmaxf(a2.z * __ldg(&bA[kb + lcA + 6]) + __ldg(&bBv[kb + lcA + 6]), 0.f);
            As[lrA][lcA + 7] = fmaxf(a2.w * __ldg(&bA[kb + lcA + 7]) + __ldg(&bBv[kb + lcA + 7]), 0.f);
            Ws[lrW][lcW + 0] = wv.x; Ws[lrW][lcW + 1] = wv.y;
            Ws[lrW][lcW + 2] = wv.z; Ws[lrW][lcW + 3] = wv.w;
            __syncthreads();
#pragma unroll
            for (int k = 0; k < 16; k++) {
                float a[8], b[4];
#pragma unroll
                for (int i = 0; i < 8; i++) a[i] = As[ty * 8 + i][k];
#pragma unroll
                for (int j = 0; j < 4; j++) b[j] = Ws[tx * 4 + j][k];
#pragma unroll
                for (int i = 0; i < 8; i++)
#pragma unroll
                    for (int j = 0; j < 4; j++) acc[i][j] += a[i] * b[j];
            }
            __syncthreads();
        }
#pragma unroll
        for (int i = 0; i < 8; i++) {
            int m = m0 + ty * 8 + i;
            float gate = g_gates[m * 4 + s + 1];
#pragma unroll
            for (int j = 0; j < 4; j++)
                tot[i][j] += gate * (acc[i][j] + __ldg(&ob[n0 + tx * 4 + j]));
        }
    }

#pragma unroll
    for (int i = 0; i < 8; i++) {
        int m = m0 + ty * 8 + i;
#pragma unroll
        for (int j = 0; j < 4; j++)
            out[(size_t)m * DD + n0 + tx * 4 + j] = tot[i][j];
    }
}

// ---------------- launch ----------------
extern "C" void kernel_launch(void* const* d_in, const int* in_sizes, int n_in,
                              void* d_out, int out_size)
{
    const float* x      = (const float*)d_in[0];
    const int*   task   = (const int*)d_in[1];
    const float* r_wih  = (const float*)d_in[2];
    const float* r_whh  = (const float*)d_in[3];
    const float* r_bih  = (const float*)d_in[4];
    const float* r_bhh  = (const float*)d_in[5];
    const float* r_ow   = (const float*)d_in[6];
    const float* r_ob   = (const float*)d_in[7];
    const float* e1_wih = (const float*)d_in[8];
    const float* e1_whh = (const float*)d_in[9];
    const float* e1_bih = (const float*)d_in[10];
    const float* e1_bhh = (const float*)d_in[11];
    const float* e1_bng = (const float*)d_in[12];
    const float* e1_bnb = (const float*)d_in[13];
    const float* e1_ow  = (const float*)d_in[14];
    const float* e1_ob  = (const float*)d_in[15];
    const float* e2_wih = (const float*)d_in[16];
    const float* e2_whh = (const float*)d_in[17];
    const float* e2_bih = (const float*)d_in[18];
    const float* e2_bhh = (const float*)d_in[19];
    const float* e2_bng = (const float*)d_in[20];
    const float* e2_bnb = (const float*)d_in[21];
    const float* e2_ow  = (const float*)d_in[22];
    const float* e2_ob  = (const float*)d_in[23];
    const float* e3_wih = (const float*)d_in[24];
    const float* e3_whh = (const float*)d_in[25];
    const float* e3_bih = (const float*)d_in[26];
    const float* e3_bhh = (const float*)d_in[27];
    const float* e3_bng = (const float*)d_in[28];
    const float* e3_bnb = (const float*)d_in[29];
    const float* e3_ow  = (const float*)d_in[30];
    const float* e3_ob  = (const float*)d_in[31];

    float* out = (float*)d_out;
    float* raw = out + (size_t)NN * DD;
    float* tl  = raw + (size_t)NN * 4;

    k_zero<<<1, 256>>>();

    cudaFuncSetAttribute(k_fat, cudaFuncAttributeNonPortableClusterSizeAllowed, 1);
    cudaLaunchConfig_t cfg = {};
    cfg.gridDim = dim3(3504, 1, 1);
    cfg.blockDim = dim3(512, 1, 1);
    cfg.dynamicSmemBytes = 0;
    cfg.stream = 0;
    cudaLaunchAttribute lattr[1];
    lattr[0].id = cudaLaunchAttributeClusterDimension;
    lattr[0].val.clusterDim.x = 16;
    lattr[0].val.clusterDim.y = 1;
    lattr[0].val.clusterDim.z = 1;
    cfg.attrs = lattr;
    cfg.numAttrs = 1;
    cudaLaunchKernelEx(&cfg, k_fat,
                       x, r_wih, r_bih, e1_wih, e1_bih, e2_wih, e2_bih, e3_wih, e3_bih,
                       r_whh, r_bhh, e1_whh, e1_bhh, e2_whh, e2_bhh, e3_whh, e3_bhh);

    k_post1<<<736, 256>>>(r_ow, r_ob, task, raw);
    k_post2<<<8, 128>>>(e1_bng, e1_bnb, e2_bng, e2_bnb, e3_bng, e3_bnb, tl);
    k_epi_all<<<dim3(8, 32), 256>>>(e1_ow, e1_ob, e2_ow, e2_ob, e3_ow, e3_ob, x, out);
}